// round 15
// baseline (speedup 1.0000x reference)
#include <cuda_runtime.h>
#include <cuda_fp16.h>
#include <math.h>
#include <stdint.h>

#define T_TOK   8192
#define CIN     768
#define HID     3072
#define NEXP    8
#define DLOW    192
#define MAIN_SIZE (8 * 768 * 1024)
#define BSTR    (CIN * 1024)

#define BM 128
#define BN 128
#define BK 64
#define ROWFH 72
#define STAGE_H ((BM + BN) * ROWFH)
#define SMEM_BYTES (3 * STAGE_H * 2)

#define FB_STAGE ((128 + 64) * ROWFH)
#define FB_SMEM  (3 * FB_STAGE * 2)

#define DCHUNKS 8
#define DPER    (DLOW / DCHUNKS)

/* ---------------- scratch ---------------- */
__device__ float  g_xT[(size_t)T_TOK * CIN];
__device__ __half g_xTr[(size_t)T_TOK * CIN];
__device__ __half g_H[(size_t)T_TOK * HID];
__device__ __half g_wcat[(size_t)HID * CIN];
__device__ __half g_wdh[(size_t)NEXP * DLOW * CIN];
__device__ __half g_w2r[(size_t)CIN * HID];
__device__ __half g_wupT[(size_t)NEXP * CIN * DLOW];
__device__ __half g_Bex[(size_t)NEXP * T_TOK * DLOW];
__device__ float  g_aoe[(size_t)MAIN_SIZE];
__device__ double g_Cp[NEXP][DCHUNKS][CIN];
__device__ float  g_C[CIN * NEXP];
__device__ float  g_probsT[NEXP * T_TOK];
__device__ int    g_cnt[NEXP];
__device__ int    g_btok[NEXP * T_TOK];
__device__ float  g_bwt[NEXP * T_TOK];

__device__ __forceinline__ float gelu_exact(float v) {
    return 0.5f * v * (1.0f + erff(v * 0.7071067811865475f));
}
__device__ __forceinline__ uint32_t smem_u32(const void* p) {
    uint32_t a;
    asm("{ .reg .u64 t; cvta.to.shared.u64 t, %1; cvt.u32.u64 %0, t; }" : "=r"(a) : "l"(p));
    return a;
}
__device__ __forceinline__ void ldsm4(uint32_t& r0, uint32_t& r1, uint32_t& r2,
                                      uint32_t& r3, uint32_t addr) {
    asm volatile("ldmatrix.sync.aligned.m8n8.x4.shared.b16 {%0,%1,%2,%3}, [%4];"
                 : "=r"(r0), "=r"(r1), "=r"(r2), "=r"(r3) : "r"(addr));
}
__device__ __forceinline__ void mma16h(float* c, const uint32_t* a, uint32_t b0, uint32_t b1) {
    asm volatile("mma.sync.aligned.m16n8k16.row.col.f32.f16.f16.f32 "
                 "{%0,%1,%2,%3}, {%4,%5,%6,%7}, {%8,%9}, {%0,%1,%2,%3};"
                 : "+f"(c[0]), "+f"(c[1]), "+f"(c[2]), "+f"(c[3])
                 : "r"(a[0]), "r"(a[1]), "r"(a[2]), "r"(a[3]), "r"(b0), "r"(b1));
}
__device__ __forceinline__ void cp16(uint32_t dst, const void* src) {
    asm volatile("cp.async.cg.shared.global [%0], [%1], 16;" :: "r"(dst), "l"(src) : "memory");
}
__device__ __forceinline__ void cp_commit() { asm volatile("cp.async.commit_group;" ::: "memory"); }
__device__ __forceinline__ void cp_wait1()  { asm volatile("cp.async.wait_group 1;" ::: "memory"); }
__device__ __forceinline__ void cp_wait0()  { asm volatile("cp.async.wait_group 0;" ::: "memory"); }

/* ---------------- prep ---------------- */
#define N4_W1 ((HID * CIN) / 4)
#define N4_WD ((NEXP * DLOW * CIN) / 4)
#define N4_W2 ((CIN * HID) / 4)
#define N4_AOE (MAIN_SIZE / 4)
#define N4_TOT (N4_W1 + N4_WD + N4_W2 + N4_AOE)

__global__ __launch_bounds__(256)
void prep_kernel(const float* __restrict__ w1, const float* __restrict__ wd,
                 const float* __restrict__ w2) {
    if (blockIdx.x == 0 && threadIdx.x < NEXP) g_cnt[threadIdx.x] = 0;
    const int stride = gridDim.x * 256;
    for (int i = blockIdx.x * 256 + threadIdx.x; i < N4_TOT; i += stride) {
        const float4* src;
        __half2* dst;
        if (i < N4_W1) {
            src = (const float4*)w1 + i;
            dst = (__half2*)g_wcat + i * 2;
        } else if (i < N4_W1 + N4_WD) {
            src = (const float4*)wd + (i - N4_W1);
            dst = (__half2*)g_wdh + (i - N4_W1) * 2;
        } else if (i < N4_W1 + N4_WD + N4_W2) {
            src = (const float4*)w2 + (i - N4_W1 - N4_WD);
            dst = (__half2*)g_w2r + (i - N4_W1 - N4_WD) * 2;
        } else {
            ((float4*)g_aoe)[i - N4_W1 - N4_WD - N4_W2] = make_float4(0.f, 0.f, 0.f, 0.f);
            continue;
        }
        float4 v = *src;
        dst[0] = __floats2half2_rn(v.x, v.y);
        dst[1] = __floats2half2_rn(v.z, v.w);
    }
}

__global__ void transpose_x_kernel(const float* __restrict__ x) {
    __shared__ float tb[32][33];
    const int b = blockIdx.z, p0 = blockIdx.x * 32, k0 = blockIdx.y * 32;
    const int tx = threadIdx.x, ty0 = threadIdx.y;
#pragma unroll
    for (int i = 0; i < 4; i++) {
        const int ty = ty0 + i * 8;
        tb[ty][tx] = x[(size_t)b * BSTR + (size_t)(k0 + ty) * 1024 + p0 + tx];
    }
    __syncthreads();
#pragma unroll
    for (int i = 0; i < 4; i++) {
        const int ty = ty0 + i * 8;
        const float v = tb[tx][ty];
        const size_t idx = (size_t)(b * 1024 + p0 + ty) * CIN + k0 + tx;
        g_xT[idx]  = v;
        g_xTr[idx] = __float2half_rn(v);
    }
}

__global__ void wupT_kernel(const float* __restrict__ wup) {
    __shared__ float tb[32][33];
    const int e = blockIdx.z, m0 = blockIdx.x * 32, d0 = blockIdx.y * 32;
    const int tx = threadIdx.x, ty0 = threadIdx.y;
#pragma unroll
    for (int i = 0; i < 4; i++) {
        const int ty = ty0 + i * 8;
        tb[ty][tx] = wup[((size_t)e * DLOW + d0 + ty) * CIN + m0 + tx];
    }
    __syncthreads();
#pragma unroll
    for (int i = 0; i < 4; i++) {
        const int ty = ty0 + i * 8;
        g_wupT[(size_t)e * CIN * DLOW + (size_t)(m0 + ty) * DLOW + d0 + tx] =
            __float2half_rn(tb[tx][ty]);
    }
}

__global__ void precompC_part_kernel(const float* __restrict__ wd,
                                     const float* __restrict__ r) {
    __shared__ float rs[DPER];
    const int e = blockIdx.x, yc = blockIdx.y, k = threadIdx.x;
    const int d0 = yc * DPER;
    if (k < DPER) rs[k] = r[d0 + k];
    __syncthreads();
    const float* base = wd + (size_t)(e * DLOW + d0) * CIN + k;
    double s = 0.0;
#pragma unroll
    for (int d = 0; d < DPER; d++)
        s += (double)base[(size_t)d * CIN] * (double)rs[d];
    g_Cp[e][yc][k] = s;
}

__global__ __launch_bounds__(256)
void precompC_reduce_kernel() {
    const int i = blockIdx.x * 256 + threadIdx.x;
    if (i >= CIN * NEXP) return;
    const int k = i >> 3, e = i & 7;
    double s = 0.0;
#pragma unroll
    for (int c = 0; c < DCHUNKS; c++) s += g_Cp[e][c][k];
    g_C[k * NEXP + e] = (float)s;
}

/* router v4 */
#define CS_REG 1536
#define CS_PAD 1544
__global__ __launch_bounds__(256)
void router_kernel() {
    __shared__ float Cs[4 * CS_PAD];
    const int tid = threadIdx.x;
    for (int i = tid; i < CIN * NEXP; i += 256) {
        const int sub = i / CS_REG, rem = i - sub * CS_REG;
        Cs[sub * CS_PAD + rem] = g_C[i];
    }
    __syncthreads();

    const int sub = tid & 3;
    const int t = blockIdx.x * 64 + (tid >> 2);
    const float* xp = g_xT + (size_t)t * CIN + sub * 192;
    const float* cbase = Cs + sub * CS_PAD;

    float lg[NEXP];
#pragma unroll
    for (int e = 0; e < NEXP; e++) lg[e] = 0.f;
    for (int k = 0; k < 192; k += 4) {
        const float4 xv = *(const float4*)(xp + k);
        const float* cp = cbase + k * NEXP;
#pragma unroll
        for (int e = 0; e < NEXP; e++)
            lg[e] += xv.x * cp[e] + xv.y * cp[NEXP + e]
                   + xv.z * cp[2 * NEXP + e] + xv.w * cp[3 * NEXP + e];
    }
#pragma unroll
    for (int off = 1; off < 4; off <<= 1)
#pragma unroll
        for (int e = 0; e < NEXP; e++)
            lg[e] += __shfl_xor_sync(0xffffffffu, lg[e], off);

    if (sub == 0) {
        float mx = lg[0];
#pragma unroll
        for (int e = 1; e < NEXP; e++) mx = fmaxf(mx, lg[e]);
        float p[NEXP], s = 0.f;
#pragma unroll
        for (int e = 0; e < NEXP; e++) { p[e] = expf(lg[e] - mx); s += p[e]; }
        const float inv = 1.f / s;
#pragma unroll
        for (int e = 0; e < NEXP; e++) { p[e] *= inv; g_probsT[e * T_TOK + t] = p[e]; }

        int i1 = 0;
#pragma unroll
        for (int e = 1; e < NEXP; e++) if (p[e] > p[i1]) i1 = e;
        int i2 = (i1 == 0) ? 1 : 0;
#pragma unroll
        for (int e = 0; e < NEXP; e++) if (e != i1 && p[e] > p[i2]) i2 = e;

        const float wsum = p[i1] + p[i2];
        int pos = atomicAdd(&g_cnt[i1], 1);
        g_btok[i1 * T_TOK + pos] = t;
        g_bwt [i1 * T_TOK + pos] = p[i1] / wsum;
        pos = atomicAdd(&g_cnt[i2], 1);
        g_btok[i2 * T_TOK + pos] = t;
        g_bwt [i2 * T_TOK + pos] = p[i2] / wsum;
    }
}

/* -------- gathered per-expert feats GEMM -> g_Bex ---------------------- */
__global__ __launch_bounds__(256)
void feats_gemm_kernel()
{
    extern __shared__ __half smf[];
    __shared__ int stok[128];

    const int e   = blockIdx.z;
    const int n_e = g_cnt[e];
    const int p0  = blockIdx.y * 128;
    if (p0 >= n_e) return;
    const int d0  = blockIdx.x * 64;

    const int tid  = threadIdx.x;
    const int lane = tid & 31, warp = tid >> 5;
    const int wm = warp >> 2, wn = warp & 3;

    if (tid < 128) {
        const int j = p0 + tid;
        stok[tid] = (j < n_e) ? g_btok[e * T_TOK + j] : 0;
    }
    __syncthreads();

    const __half* pBg = g_wdh + (size_t)(e * DLOW + d0) * CIN;

    float c[4][2][4];
#pragma unroll
    for (int i = 0; i < 4; i++)
#pragma unroll
        for (int j = 0; j < 2; j++)
#pragma unroll
            for (int q = 0; q < 4; q++) c[i][j][q] = 0.f;

#define FISSUE(KT, S) do {                                                    \
        __half* as_ = smf + (S) * FB_STAGE;                                   \
        __half* bs_ = as_ + 128 * ROWFH;                                      \
        const uint32_t au_ = smem_u32(as_);                                   \
        const uint32_t bu_ = smem_u32(bs_);                                   \
        _Pragma("unroll")                                                     \
        for (int i_ = 0; i_ < 4; i_++) {                                      \
            const int c_ = tid + 256 * i_;                                    \
            const int r_ = c_ >> 3, sg_ = c_ & 7;                             \
            cp16(au_ + (uint32_t)(r_ * ROWFH + sg_ * 8) * 2u,                 \
                 g_xTr + (size_t)stok[r_] * CIN + (KT) * BK + sg_ * 8);       \
        }                                                                     \
        _Pragma("unroll")                                                     \
        for (int i_ = 0; i_ < 2; i_++) {                                      \
            const int c_ = tid + 256 * i_;                                    \
            const int r_ = c_ >> 3, sg_ = c_ & 7;                             \
            cp16(bu_ + (uint32_t)(r_ * ROWFH + sg_ * 8) * 2u,                 \
                 pBg + (size_t)r_ * CIN + (KT) * BK + sg_ * 8);               \
        }                                                                     \
    } while (0)

    const int NT = CIN / BK;
    FISSUE(0, 0); cp_commit();
    FISSUE(1, 1); cp_commit();

    const int arow  = (lane & 15);
    const int akoff = ((lane >> 4) & 1) * 8;
    const int brow  = (lane & 7) + ((lane >> 4) & 1) * 8;
    const int bkoff = ((lane >> 3) & 1) * 8;

    for (int kt = 0; kt < NT; kt++) {
        if (kt == NT - 1) cp_wait0(); else cp_wait1();
        __syncthreads();
        if (kt + 2 < NT) { FISSUE(kt + 2, (kt + 2) % 3); cp_commit(); }

        const int s = kt % 3;
        const uint32_t abase = smem_u32(smf + s * FB_STAGE);
        const uint32_t bbase = abase + 128 * ROWFH * 2u;
#pragma unroll
        for (int ks = 0; ks < 4; ks++) {
            const int kh = ks * 16;
            uint32_t a[4][4], bf[4];
#pragma unroll
            for (int mf = 0; mf < 4; mf++) {
                const int row = wm * 64 + mf * 16 + arow;
                ldsm4(a[mf][0], a[mf][1], a[mf][2], a[mf][3],
                      abase + (uint32_t)(row * ROWFH + kh + akoff) * 2u);
            }
            {
                const int row = wn * 16 + brow;
                ldsm4(bf[0], bf[1], bf[2], bf[3],
                      bbase + (uint32_t)(row * ROWFH + kh + bkoff) * 2u);
            }
#pragma unroll
            for (int mf = 0; mf < 4; mf++) {
                mma16h(c[mf][0], a[mf], bf[0], bf[1]);
                mma16h(c[mf][1], a[mf], bf[2], bf[3]);
            }
        }
    }
#undef FISSUE

#pragma unroll
    for (int mf = 0; mf < 4; mf++)
#pragma unroll
        for (int nf = 0; nf < 2; nf++)
#pragma unroll
            for (int h = 0; h < 2; h++) {
                const int pl = wm * 64 + mf * 16 + (lane >> 2) + h * 8;
                const int gd = d0 + wn * 16 + nf * 8 + (lane & 3) * 2;
                const int pos = p0 + pl;
                __half2 hv = (pos < n_e)
                    ? __floats2half2_rn(gelu_exact(c[mf][nf][h * 2]),
                                        gelu_exact(c[mf][nf][h * 2 + 1]))
                    : __floats2half2_rn(0.f, 0.f);
                *(__half2*)&g_Bex[((size_t)e * T_TOK + pos) * DLOW + gd] = hv;
            }
}

/* ---------------- fp16 MMA mainloop macros ---------------- */
#define ISSUE(KT, S, LDK) do {                                                \
        __half* as_ = smf + (S) * STAGE_H;                                    \
        __half* bs_ = as_ + BM * ROWFH;                                       \
        const uint32_t au_ = smem_u32(as_);                                   \
        const uint32_t bu_ = smem_u32(bs_);                                   \
        _Pragma("unroll")                                                     \
        for (int i_ = 0; i_ < 4; i_++) {                                      \
            const int c_ = tid + 256 * i_;                                    \
            const int r_ = c_ >> 3, sg_ = c_ & 7;                             \
            cp16(au_ + (uint32_t)(r_ * ROWFH + sg_ * 8) * 2u,                 \
                 pAg + (size_t)r_ * (LDK) + (KT) * BK + sg_ * 8);             \
            cp16(bu_ + (uint32_t)(r_ * ROWFH + sg_ * 8) * 2u,                 \
                 pBg + (size_t)r_ * (LDK) + (KT) * BK + sg_ * 8);             \
        }                                                                     \
    } while (0)

#define MAINLOOP_BODY(NTv, LDK)                                               \
    ISSUE(0, 0, LDK); cp_commit();                                            \
    ISSUE(1, 1, LDK); cp_commit();                                            \
    const int arow  = (lane & 15);                                            \
    const int akoff = ((lane >> 4) & 1) * 8;                                  \
    const int brow  = (lane & 7) + ((lane >> 4) & 1) * 8;                     \
    const int bkoff = ((lane >> 3) & 1) * 8;                                  \
    for (int kt = 0; kt < (NTv); kt++) {                                      \
        if (kt == (NTv) - 1) cp_wait0(); else cp_wait1();                     \
        __syncthreads();                                                      \
        if (kt + 2 < (NTv)) { ISSUE(kt + 2, (kt + 2) % 3, LDK); cp_commit(); }\
        const int s = kt % 3;                                                 \
        const uint32_t abase = smem_u32(smf + s * STAGE_H);                   \
        const uint32_t bbase = abase + BM * ROWFH * 2u;                       \
        _Pragma("unroll")                                                     \
        for (int ks = 0; ks < 4; ks++) {                                      \
            const int kh = ks * 16;                                           \
            uint32_t a[4][4], bf[2][4];                                       \
            _Pragma("unroll")                                                 \
            for (int mf = 0; mf < 4; mf++) {                                  \
                const int row = wm * 64 + mf * 16 + arow;                     \
                ldsm4(a[mf][0], a[mf][1], a[mf][2], a[mf][3],                 \
                      abase + (uint32_t)(row * ROWFH + kh + akoff) * 2u);     \
            }                                                                 \
            _Pragma("unroll")                                                 \
            for (int np = 0; np < 2; np++) {                                  \
                const int row = wn * 32 + np * 16 + brow;                     \
                ldsm4(bf[np][0], bf[np][1], bf[np][2], bf[np][3],             \
                      bbase + (uint32_t)(row * ROWFH + kh + bkoff) * 2u);     \
            }                                                                 \
            _Pragma("unroll")                                                 \
            for (int mf = 0; mf < 4; mf++)                                    \
                _Pragma("unroll")                                             \
                for (int nf = 0; nf < 4; nf++)                                \
                    mma16h(c[mf][nf], a[mf],                                  \
                           bf[nf >> 1][(nf & 1) * 2],                         \
                           bf[nf >> 1][(nf & 1) * 2 + 1]);                    \
        }                                                                     \
    }

/* ---------------- H GEMM ---------------- */
__global__ __launch_bounds__(256, 2)
void gemm0_kernel(const float* __restrict__ bias)
{
    extern __shared__ __half smf[];
    const int tid  = threadIdx.x;
    const int lane = tid & 31, warp = tid >> 5;
    const int wm = warp >> 2, wn = warp & 3;
    const int m0 = blockIdx.x * BM, n0 = blockIdx.y * BN;

    const __half* pAg = g_xTr + (size_t)m0 * CIN;
    const __half* pBg = g_wcat + (size_t)n0 * CIN;

    float c[4][4][4];
#pragma unroll
    for (int i = 0; i < 4; i++)
#pragma unroll
        for (int j = 0; j < 4; j++)
#pragma unroll
            for (int q = 0; q < 4; q++) c[i][j][q] = 0.f;

    MAINLOOP_BODY(CIN / BK, CIN)

#pragma unroll
    for (int mf = 0; mf < 4; mf++)
#pragma unroll
        for (int nf = 0; nf < 4; nf++)
#pragma unroll
            for (int h = 0; h < 2; h++) {
                const int gm = m0 + wm * 64 + mf * 16 + (lane >> 2) + h * 8;
                const int gn = n0 + wn * 32 + nf * 8 + (lane & 3) * 2;
                const float v0 = gelu_exact(c[mf][nf][h * 2 + 0] + bias[gn]);
                const float v1 = gelu_exact(c[mf][nf][h * 2 + 1] + bias[gn + 1]);
                *(__half2*)&g_H[(size_t)gm * HID + gn] = __floats2half2_rn(v0, v1);
            }
}

/* ---------------- expert GEMMs (side stream, into g_aoe) --------------- */
__global__ __launch_bounds__(256)
void expert_kernel()
{
    extern __shared__ __half smf[];
    __shared__ int   stok[128];
    __shared__ float swt[128];

    const int e   = blockIdx.z;
    const int n_e = g_cnt[e];
    const int n0  = blockIdx.y * 128;
    if (n0 >= n_e) return;
    const int m0  = blockIdx.x * BM;

    const int tid  = threadIdx.x;
    const int lane = tid & 31, warp = tid >> 5;
    const int wm = warp >> 2, wn = warp & 3;

    if (tid < 128) {
        const int j = n0 + tid;
        stok[tid] = (j < n_e) ? g_btok[e * T_TOK + j] : -1;
        swt [tid] = (j < n_e) ? g_bwt [e * T_TOK + j] : 0.f;
    }
    __syncthreads();

    const __half* pAg = g_wupT + (size_t)e * CIN * DLOW + (size_t)m0 * DLOW;
    const __half* pBg = g_Bex  + ((size_t)e * T_TOK + n0) * DLOW;

    float c[4][4][4];
#pragma unroll
    for (int i = 0; i < 4; i++)
#pragma unroll
        for (int j = 0; j < 4; j++)
#pragma unroll
            for (int q = 0; q < 4; q++) c[i][j][q] = 0.f;

    MAINLOOP_BODY(DLOW / BK, DLOW)

#pragma unroll
    for (int mf = 0; mf < 4; mf++)
#pragma unroll
        for (int nf = 0; nf < 4; nf++)
#pragma unroll
            for (int h = 0; h < 2; h++) {
                const int gm = m0 + wm * 64 + mf * 16 + (lane >> 2) + h * 8;
                const int col0 = wn * 32 + nf * 8 + (lane & 3) * 2;
#pragma unroll
                for (int q = 0; q < 2; q++) {
                    const int col = col0 + q;
                    const int tk = stok[col];
                    if (tk < 0) continue;
                    atomicAdd(&g_aoe[(size_t)(tk >> 10) * BSTR +
                                     (size_t)gm * 1024 + (tk & 1023)],
                              c[mf][nf][h * 2 + q] * swt[col]);
                }
            }
}

/* ---------------- out-GEMM: out = x + shared + b2 + aoe ---------------- */
__global__ __launch_bounds__(256, 2)
void out_gemm_kernel(const float* __restrict__ b2, const float* __restrict__ xres,
                     float* __restrict__ outp)
{
    extern __shared__ __half smf[];
    const int tid  = threadIdx.x;
    const int lane = tid & 31, warp = tid >> 5;
    const int wm = warp >> 2, wn = warp & 3;
    const int m0 = blockIdx.x * BM, n0 = blockIdx.y * BN;

    const __half* pAg = g_w2r + (size_t)m0 * HID;
    const __half* pBg = g_H + (size_t)n0 * HID;

    float c[4][4][4];
#pragma unroll
    for (int i = 0; i < 4; i++)
#pragma unroll
        for (int j = 0; j < 4; j++)
#pragma unroll
            for (int q = 0; q < 4; q++) c[i][j][q] = 0.f;

    MAINLOOP_BODY(HID / BK, HID)

#pragma unroll
    for (int mf = 0; mf < 4; mf++)
#pragma unroll
        for (int nf = 0; nf < 4; nf++)
#pragma unroll
            for (int h = 0; h < 2; h++) {
                const int gm = m0 + wm * 64 + mf * 16 + (lane >> 2) + h * 8;
                const int gn = n0 + wn * 32 + nf * 8 + (lane & 3) * 2;
                const size_t off = (size_t)(gn >> 10) * BSTR + (size_t)gm * 1024 + (gn & 1023);
                const float2 xr = *(const float2*)&xres[off];
                const float2 ao = *(const float2*)&g_aoe[off];
                const float bv = b2[gm];
                *(float2*)&outp[off] =
                    make_float2(xr.x + c[mf][nf][h * 2 + 0] + bv + ao.x,
                                xr.y + c[mf][nf][h * 2 + 1] + bv + ao.y);
            }
}

/* ---------------- aux loss ---------------- */
__global__ __launch_bounds__(256)
void aux_kernel(float* __restrict__ out, int out_size)
{
    __shared__ float red[NEXP][256];
    const int tid = threadIdx.x;
    for (int e = 0; e < NEXP; e++) {
        float s = 0.f;
        for (int t = tid; t < T_TOK; t += 256) s += g_probsT[e * T_TOK + t];
        red[e][tid] = s;
    }
    __syncthreads();
    for (int off = 128; off; off >>= 1) {
        if (tid < off)
            for (int e = 0; e < NEXP; e++) red[e][tid] += red[e][tid + off];
        __syncthreads();
    }
    if (tid == 0) {
        float aux = 0.f;
        for (int e = 0; e < NEXP; e++)
            aux += (red[e][0] / (float)T_TOK) * ((float)g_cnt[e] / (float)T_TOK);
        aux *= (float)NEXP;
        for (int i = MAIN_SIZE; i < out_size; i++) out[i] = aux;
    }
}

/* ---------------- launch ---------------- */
extern "C" void kernel_launch(void* const* d_in, const int* in_sizes, int n_in,
                              void* d_out, int out_size)
{
    const float* x        = (const float*)d_in[0];
    const float* w1       = (const float*)d_in[1];
    const float* b1       = (const float*)d_in[2];
    const float* w2       = (const float*)d_in[3];
    const float* b2       = (const float*)d_in[4];
    const float* w_down   = (const float*)d_in[5];
    const float* router_w = (const float*)d_in[6];
    const float* w_up     = (const float*)d_in[7];
    float* out = (float*)d_out;

    static cudaStream_t s2 = nullptr;
    static cudaEvent_t evFork = nullptr, evSide = nullptr;
    if (!s2) {
        cudaStreamCreateWithFlags(&s2, cudaStreamNonBlocking);
        cudaEventCreateWithFlags(&evFork, cudaEventDisableTiming);
        cudaEventCreateWithFlags(&evSide, cudaEventDisableTiming);
        cudaFuncSetAttribute(gemm0_kernel, cudaFuncAttributeMaxDynamicSharedMemorySize, SMEM_BYTES);
        cudaFuncSetAttribute(out_gemm_kernel, cudaFuncAttributeMaxDynamicSharedMemorySize, SMEM_BYTES);
        cudaFuncSetAttribute(expert_kernel, cudaFuncAttributeMaxDynamicSharedMemorySize, SMEM_BYTES);
        cudaFuncSetAttribute(feats_gemm_kernel, cudaFuncAttributeMaxDynamicSharedMemorySize, FB_SMEM);
    }

    prep_kernel<<<592, 256>>>(w1, w_down, w2);
    transpose_x_kernel<<<dim3(32, 24, 8), dim3(32, 8)>>>(x);
    cudaEventRecord(evFork, 0);

    /* side stream: router chain + wupT + feats + expert GEMMs (into g_aoe) */
    cudaStreamWaitEvent(s2, evFork, 0);
    precompC_part_kernel<<<dim3(NEXP, DCHUNKS), CIN, 0, s2>>>(w_down, router_w);
    precompC_reduce_kernel<<<(CIN * NEXP + 255) / 256, 256, 0, s2>>>();
    router_kernel<<<128, 256, 0, s2>>>();
    aux_kernel<<<1, 256, 0, s2>>>(out, out_size);
    wupT_kernel<<<dim3(24, 6, 8), dim3(32, 8), 0, s2>>>(w_up);
    feats_gemm_kernel<<<dim3(DLOW / 64, 64, NEXP), 256, FB_SMEM, s2>>>();
    expert_kernel<<<dim3(6, 64, NEXP), 256, SMEM_BYTES, s2>>>();
    cudaEventRecord(evSide, s2);

    gemm0_kernel<<<dim3(64, HID / 128), 256, SMEM_BYTES>>>(b1);

    /* out-GEMM folds g_aoe in its epilogue */
    cudaStreamWaitEvent(0, evSide, 0);
    out_gemm_kernel<<<dim3(6, 64), 256, SMEM_BYTES>>>(b2, x, out);
}

// round 16
// speedup vs baseline: 1.1780x; 1.1780x over previous
#include <cuda_runtime.h>
#include <cuda_fp16.h>
#include <math.h>
#include <stdint.h>

#define T_TOK   8192
#define CIN     768
#define HID     3072
#define NEXP    8
#define DLOW    192
#define MAIN_SIZE (8 * 768 * 1024)
#define BSTR    (CIN * 1024)

#define BM 128
#define BN 128
#define BK 64
#define ROWFH 72
#define STAGE_H ((BM + BN) * ROWFH)
#define SMEM_BYTES (3 * STAGE_H * 2)

#define FB_STAGE ((128 + 64) * ROWFH)
#define FB_SMEM  (3 * FB_STAGE * 2)

#define DCHUNKS 8
#define DPER    (DLOW / DCHUNKS)

/* ---------------- scratch ---------------- */
__device__ float  g_xT[(size_t)T_TOK * CIN];
__device__ __half g_xTr[(size_t)T_TOK * CIN];
__device__ __half g_H[(size_t)T_TOK * HID];
__device__ __half g_wcat[(size_t)HID * CIN];
__device__ __half g_wdh[(size_t)NEXP * DLOW * CIN];
__device__ __half g_w2r[(size_t)CIN * HID];
__device__ __half g_wupT[(size_t)NEXP * CIN * DLOW];
__device__ __half g_Bex[(size_t)NEXP * T_TOK * DLOW];
__device__ float  g_aoe[(size_t)MAIN_SIZE];
__device__ double g_Cp[NEXP][DCHUNKS][CIN];
__device__ float  g_C[CIN * NEXP];
__device__ float  g_probsT[NEXP * T_TOK];
__device__ int    g_cnt[NEXP];
__device__ int    g_btok[NEXP * T_TOK];
__device__ float  g_bwt[NEXP * T_TOK];

__device__ __forceinline__ float gelu_exact(float v) {
    return 0.5f * v * (1.0f + erff(v * 0.7071067811865475f));
}
__device__ __forceinline__ uint32_t smem_u32(const void* p) {
    uint32_t a;
    asm("{ .reg .u64 t; cvta.to.shared.u64 t, %1; cvt.u32.u64 %0, t; }" : "=r"(a) : "l"(p));
    return a;
}
__device__ __forceinline__ void ldsm4(uint32_t& r0, uint32_t& r1, uint32_t& r2,
                                      uint32_t& r3, uint32_t addr) {
    asm volatile("ldmatrix.sync.aligned.m8n8.x4.shared.b16 {%0,%1,%2,%3}, [%4];"
                 : "=r"(r0), "=r"(r1), "=r"(r2), "=r"(r3) : "r"(addr));
}
__device__ __forceinline__ void mma16h(float* c, const uint32_t* a, uint32_t b0, uint32_t b1) {
    asm volatile("mma.sync.aligned.m16n8k16.row.col.f32.f16.f16.f32 "
                 "{%0,%1,%2,%3}, {%4,%5,%6,%7}, {%8,%9}, {%0,%1,%2,%3};"
                 : "+f"(c[0]), "+f"(c[1]), "+f"(c[2]), "+f"(c[3])
                 : "r"(a[0]), "r"(a[1]), "r"(a[2]), "r"(a[3]), "r"(b0), "r"(b1));
}
__device__ __forceinline__ void cp16(uint32_t dst, const void* src) {
    asm volatile("cp.async.cg.shared.global [%0], [%1], 16;" :: "r"(dst), "l"(src) : "memory");
}
__device__ __forceinline__ void cp_commit() { asm volatile("cp.async.commit_group;" ::: "memory"); }
__device__ __forceinline__ void cp_wait1()  { asm volatile("cp.async.wait_group 1;" ::: "memory"); }
__device__ __forceinline__ void cp_wait0()  { asm volatile("cp.async.wait_group 0;" ::: "memory"); }

/* ---------------- prep ---------------- */
#define N4_W1 ((HID * CIN) / 4)
#define N4_WD ((NEXP * DLOW * CIN) / 4)
#define N4_W2 ((CIN * HID) / 4)
#define N4_AOE (MAIN_SIZE / 4)
#define N4_TOT (N4_W1 + N4_WD + N4_W2 + N4_AOE)

__global__ __launch_bounds__(256)
void prep_kernel(const float* __restrict__ w1, const float* __restrict__ wd,
                 const float* __restrict__ w2) {
    if (blockIdx.x == 0 && threadIdx.x < NEXP) g_cnt[threadIdx.x] = 0;
    const int stride = gridDim.x * 256;
    for (int i = blockIdx.x * 256 + threadIdx.x; i < N4_TOT; i += stride) {
        const float4* src;
        __half2* dst;
        if (i < N4_W1) {
            src = (const float4*)w1 + i;
            dst = (__half2*)g_wcat + i * 2;
        } else if (i < N4_W1 + N4_WD) {
            src = (const float4*)wd + (i - N4_W1);
            dst = (__half2*)g_wdh + (i - N4_W1) * 2;
        } else if (i < N4_W1 + N4_WD + N4_W2) {
            src = (const float4*)w2 + (i - N4_W1 - N4_WD);
            dst = (__half2*)g_w2r + (i - N4_W1 - N4_WD) * 2;
        } else {
            ((float4*)g_aoe)[i - N4_W1 - N4_WD - N4_W2] = make_float4(0.f, 0.f, 0.f, 0.f);
            continue;
        }
        float4 v = *src;
        dst[0] = __floats2half2_rn(v.x, v.y);
        dst[1] = __floats2half2_rn(v.z, v.w);
    }
}

__global__ void transpose_x_kernel(const float* __restrict__ x) {
    __shared__ float tb[32][33];
    const int b = blockIdx.z, p0 = blockIdx.x * 32, k0 = blockIdx.y * 32;
    const int tx = threadIdx.x, ty0 = threadIdx.y;
#pragma unroll
    for (int i = 0; i < 4; i++) {
        const int ty = ty0 + i * 8;
        tb[ty][tx] = x[(size_t)b * BSTR + (size_t)(k0 + ty) * 1024 + p0 + tx];
    }
    __syncthreads();
#pragma unroll
    for (int i = 0; i < 4; i++) {
        const int ty = ty0 + i * 8;
        const float v = tb[tx][ty];
        const size_t idx = (size_t)(b * 1024 + p0 + ty) * CIN + k0 + tx;
        g_xT[idx]  = v;
        g_xTr[idx] = __float2half_rn(v);
    }
}

__global__ void wupT_kernel(const float* __restrict__ wup) {
    __shared__ float tb[32][33];
    const int e = blockIdx.z, m0 = blockIdx.x * 32, d0 = blockIdx.y * 32;
    const int tx = threadIdx.x, ty0 = threadIdx.y;
#pragma unroll
    for (int i = 0; i < 4; i++) {
        const int ty = ty0 + i * 8;
        tb[ty][tx] = wup[((size_t)e * DLOW + d0 + ty) * CIN + m0 + tx];
    }
    __syncthreads();
#pragma unroll
    for (int i = 0; i < 4; i++) {
        const int ty = ty0 + i * 8;
        g_wupT[(size_t)e * CIN * DLOW + (size_t)(m0 + ty) * DLOW + d0 + tx] =
            __float2half_rn(tb[tx][ty]);
    }
}

__global__ void precompC_part_kernel(const float* __restrict__ wd,
                                     const float* __restrict__ r) {
    __shared__ float rs[DPER];
    const int e = blockIdx.x, yc = blockIdx.y, k = threadIdx.x;
    const int d0 = yc * DPER;
    if (k < DPER) rs[k] = r[d0 + k];
    __syncthreads();
    const float* base = wd + (size_t)(e * DLOW + d0) * CIN + k;
    double s = 0.0;
#pragma unroll
    for (int d = 0; d < DPER; d++)
        s += (double)base[(size_t)d * CIN] * (double)rs[d];
    g_Cp[e][yc][k] = s;
}

__global__ __launch_bounds__(256)
void precompC_reduce_kernel() {
    const int i = blockIdx.x * 256 + threadIdx.x;
    if (i >= CIN * NEXP) return;
    const int k = i >> 3, e = i & 7;
    double s = 0.0;
#pragma unroll
    for (int c = 0; c < DCHUNKS; c++) s += g_Cp[e][c][k];
    g_C[k * NEXP + e] = (float)s;
}

/* router v4 */
#define CS_REG 1536
#define CS_PAD 1544
__global__ __launch_bounds__(256)
void router_kernel() {
    __shared__ float Cs[4 * CS_PAD];
    const int tid = threadIdx.x;
    for (int i = tid; i < CIN * NEXP; i += 256) {
        const int sub = i / CS_REG, rem = i - sub * CS_REG;
        Cs[sub * CS_PAD + rem] = g_C[i];
    }
    __syncthreads();

    const int sub = tid & 3;
    const int t = blockIdx.x * 64 + (tid >> 2);
    const float* xp = g_xT + (size_t)t * CIN + sub * 192;
    const float* cbase = Cs + sub * CS_PAD;

    float lg[NEXP];
#pragma unroll
    for (int e = 0; e < NEXP; e++) lg[e] = 0.f;
    for (int k = 0; k < 192; k += 4) {
        const float4 xv = *(const float4*)(xp + k);
        const float* cp = cbase + k * NEXP;
#pragma unroll
        for (int e = 0; e < NEXP; e++)
            lg[e] += xv.x * cp[e] + xv.y * cp[NEXP + e]
                   + xv.z * cp[2 * NEXP + e] + xv.w * cp[3 * NEXP + e];
    }
#pragma unroll
    for (int off = 1; off < 4; off <<= 1)
#pragma unroll
        for (int e = 0; e < NEXP; e++)
            lg[e] += __shfl_xor_sync(0xffffffffu, lg[e], off);

    if (sub == 0) {
        float mx = lg[0];
#pragma unroll
        for (int e = 1; e < NEXP; e++) mx = fmaxf(mx, lg[e]);
        float p[NEXP], s = 0.f;
#pragma unroll
        for (int e = 0; e < NEXP; e++) { p[e] = expf(lg[e] - mx); s += p[e]; }
        const float inv = 1.f / s;
#pragma unroll
        for (int e = 0; e < NEXP; e++) { p[e] *= inv; g_probsT[e * T_TOK + t] = p[e]; }

        int i1 = 0;
#pragma unroll
        for (int e = 1; e < NEXP; e++) if (p[e] > p[i1]) i1 = e;
        int i2 = (i1 == 0) ? 1 : 0;
#pragma unroll
        for (int e = 0; e < NEXP; e++) if (e != i1 && p[e] > p[i2]) i2 = e;

        const float wsum = p[i1] + p[i2];
        int pos = atomicAdd(&g_cnt[i1], 1);
        g_btok[i1 * T_TOK + pos] = t;
        g_bwt [i1 * T_TOK + pos] = p[i1] / wsum;
        pos = atomicAdd(&g_cnt[i2], 1);
        g_btok[i2 * T_TOK + pos] = t;
        g_bwt [i2 * T_TOK + pos] = p[i2] / wsum;
    }
}

/* -------- gathered per-expert feats GEMM -> g_Bex ---------------------- */
__global__ __launch_bounds__(256)
void feats_gemm_kernel()
{
    extern __shared__ __half smf[];
    __shared__ int stok[128];

    const int e   = blockIdx.z;
    const int n_e = g_cnt[e];
    const int p0  = blockIdx.y * 128;
    if (p0 >= n_e) return;
    const int d0  = blockIdx.x * 64;

    const int tid  = threadIdx.x;
    const int lane = tid & 31, warp = tid >> 5;
    const int wm = warp >> 2, wn = warp & 3;

    if (tid < 128) {
        const int j = p0 + tid;
        stok[tid] = (j < n_e) ? g_btok[e * T_TOK + j] : 0;
    }
    __syncthreads();

    const __half* pBg = g_wdh + (size_t)(e * DLOW + d0) * CIN;

    float c[4][2][4];
#pragma unroll
    for (int i = 0; i < 4; i++)
#pragma unroll
        for (int j = 0; j < 2; j++)
#pragma unroll
            for (int q = 0; q < 4; q++) c[i][j][q] = 0.f;

#define FISSUE(KT, S) do {                                                    \
        __half* as_ = smf + (S) * FB_STAGE;                                   \
        __half* bs_ = as_ + 128 * ROWFH;                                      \
        const uint32_t au_ = smem_u32(as_);                                   \
        const uint32_t bu_ = smem_u32(bs_);                                   \
        _Pragma("unroll")                                                     \
        for (int i_ = 0; i_ < 4; i_++) {                                      \
            const int c_ = tid + 256 * i_;                                    \
            const int r_ = c_ >> 3, sg_ = c_ & 7;                             \
            cp16(au_ + (uint32_t)(r_ * ROWFH + sg_ * 8) * 2u,                 \
                 g_xTr + (size_t)stok[r_] * CIN + (KT) * BK + sg_ * 8);       \
        }                                                                     \
        _Pragma("unroll")                                                     \
        for (int i_ = 0; i_ < 2; i_++) {                                      \
            const int c_ = tid + 256 * i_;                                    \
            const int r_ = c_ >> 3, sg_ = c_ & 7;                             \
            cp16(bu_ + (uint32_t)(r_ * ROWFH + sg_ * 8) * 2u,                 \
                 pBg + (size_t)r_ * CIN + (KT) * BK + sg_ * 8);               \
        }                                                                     \
    } while (0)

    const int NT = CIN / BK;
    FISSUE(0, 0); cp_commit();
    FISSUE(1, 1); cp_commit();

    const int arow  = (lane & 15);
    const int akoff = ((lane >> 4) & 1) * 8;
    const int brow  = (lane & 7) + ((lane >> 4) & 1) * 8;
    const int bkoff = ((lane >> 3) & 1) * 8;

    for (int kt = 0; kt < NT; kt++) {
        if (kt == NT - 1) cp_wait0(); else cp_wait1();
        __syncthreads();
        if (kt + 2 < NT) { FISSUE(kt + 2, (kt + 2) % 3); cp_commit(); }

        const int s = kt % 3;
        const uint32_t abase = smem_u32(smf + s * FB_STAGE);
        const uint32_t bbase = abase + 128 * ROWFH * 2u;
#pragma unroll
        for (int ks = 0; ks < 4; ks++) {
            const int kh = ks * 16;
            uint32_t a[4][4], bf[4];
#pragma unroll
            for (int mf = 0; mf < 4; mf++) {
                const int row = wm * 64 + mf * 16 + arow;
                ldsm4(a[mf][0], a[mf][1], a[mf][2], a[mf][3],
                      abase + (uint32_t)(row * ROWFH + kh + akoff) * 2u);
            }
            {
                const int row = wn * 16 + brow;
                ldsm4(bf[0], bf[1], bf[2], bf[3],
                      bbase + (uint32_t)(row * ROWFH + kh + bkoff) * 2u);
            }
#pragma unroll
            for (int mf = 0; mf < 4; mf++) {
                mma16h(c[mf][0], a[mf], bf[0], bf[1]);
                mma16h(c[mf][1], a[mf], bf[2], bf[3]);
            }
        }
    }
#undef FISSUE

#pragma unroll
    for (int mf = 0; mf < 4; mf++)
#pragma unroll
        for (int nf = 0; nf < 2; nf++)
#pragma unroll
            for (int h = 0; h < 2; h++) {
                const int pl = wm * 64 + mf * 16 + (lane >> 2) + h * 8;
                const int gd = d0 + wn * 16 + nf * 8 + (lane & 3) * 2;
                const int pos = p0 + pl;
                __half2 hv = (pos < n_e)
                    ? __floats2half2_rn(gelu_exact(c[mf][nf][h * 2]),
                                        gelu_exact(c[mf][nf][h * 2 + 1]))
                    : __floats2half2_rn(0.f, 0.f);
                *(__half2*)&g_Bex[((size_t)e * T_TOK + pos) * DLOW + gd] = hv;
            }
}

/* ---------------- fp16 MMA mainloop macros ---------------- */
#define ISSUE(KT, S, LDK) do {                                                \
        __half* as_ = smf + (S) * STAGE_H;                                    \
        __half* bs_ = as_ + BM * ROWFH;                                       \
        const uint32_t au_ = smem_u32(as_);                                   \
        const uint32_t bu_ = smem_u32(bs_);                                   \
        _Pragma("unroll")                                                     \
        for (int i_ = 0; i_ < 4; i_++) {                                      \
            const int c_ = tid + 256 * i_;                                    \
            const int r_ = c_ >> 3, sg_ = c_ & 7;                             \
            cp16(au_ + (uint32_t)(r_ * ROWFH + sg_ * 8) * 2u,                 \
                 pAg + (size_t)r_ * (LDK) + (KT) * BK + sg_ * 8);             \
            cp16(bu_ + (uint32_t)(r_ * ROWFH + sg_ * 8) * 2u,                 \
                 pBg + (size_t)r_ * (LDK) + (KT) * BK + sg_ * 8);             \
        }                                                                     \
    } while (0)

#define MAINLOOP_BODY(NTv, LDK)                                               \
    ISSUE(0, 0, LDK); cp_commit();                                            \
    ISSUE(1, 1, LDK); cp_commit();                                            \
    const int arow  = (lane & 15);                                            \
    const int akoff = ((lane >> 4) & 1) * 8;                                  \
    const int brow  = (lane & 7) + ((lane >> 4) & 1) * 8;                     \
    const int bkoff = ((lane >> 3) & 1) * 8;                                  \
    for (int kt = 0; kt < (NTv); kt++) {                                      \
        if (kt == (NTv) - 1) cp_wait0(); else cp_wait1();                     \
        __syncthreads();                                                      \
        if (kt + 2 < (NTv)) { ISSUE(kt + 2, (kt + 2) % 3, LDK); cp_commit(); }\
        const int s = kt % 3;                                                 \
        const uint32_t abase = smem_u32(smf + s * STAGE_H);                   \
        const uint32_t bbase = abase + BM * ROWFH * 2u;                       \
        _Pragma("unroll")                                                     \
        for (int ks = 0; ks < 4; ks++) {                                      \
            const int kh = ks * 16;                                           \
            uint32_t a[4][4], bf[2][4];                                       \
            _Pragma("unroll")                                                 \
            for (int mf = 0; mf < 4; mf++) {                                  \
                const int row = wm * 64 + mf * 16 + arow;                     \
                ldsm4(a[mf][0], a[mf][1], a[mf][2], a[mf][3],                 \
                      abase + (uint32_t)(row * ROWFH + kh + akoff) * 2u);     \
            }                                                                 \
            _Pragma("unroll")                                                 \
            for (int np = 0; np < 2; np++) {                                  \
                const int row = wn * 32 + np * 16 + brow;                     \
                ldsm4(bf[np][0], bf[np][1], bf[np][2], bf[np][3],             \
                      bbase + (uint32_t)(row * ROWFH + kh + bkoff) * 2u);     \
            }                                                                 \
            _Pragma("unroll")                                                 \
            for (int mf = 0; mf < 4; mf++)                                    \
                _Pragma("unroll")                                             \
                for (int nf = 0; nf < 4; nf++)                                \
                    mma16h(c[mf][nf], a[mf],                                  \
                           bf[nf >> 1][(nf & 1) * 2],                         \
                           bf[nf >> 1][(nf & 1) * 2 + 1]);                    \
        }                                                                     \
    }

/* ---------------- H GEMM ---------------- */
__global__ __launch_bounds__(256, 2)
void gemm0_kernel(const float* __restrict__ bias)
{
    extern __shared__ __half smf[];
    const int tid  = threadIdx.x;
    const int lane = tid & 31, warp = tid >> 5;
    const int wm = warp >> 2, wn = warp & 3;
    const int m0 = blockIdx.x * BM, n0 = blockIdx.y * BN;

    const __half* pAg = g_xTr + (size_t)m0 * CIN;
    const __half* pBg = g_wcat + (size_t)n0 * CIN;

    float c[4][4][4];
#pragma unroll
    for (int i = 0; i < 4; i++)
#pragma unroll
        for (int j = 0; j < 4; j++)
#pragma unroll
            for (int q = 0; q < 4; q++) c[i][j][q] = 0.f;

    MAINLOOP_BODY(CIN / BK, CIN)

#pragma unroll
    for (int mf = 0; mf < 4; mf++)
#pragma unroll
        for (int nf = 0; nf < 4; nf++)
#pragma unroll
            for (int h = 0; h < 2; h++) {
                const int gm = m0 + wm * 64 + mf * 16 + (lane >> 2) + h * 8;
                const int gn = n0 + wn * 32 + nf * 8 + (lane & 3) * 2;
                const float v0 = gelu_exact(c[mf][nf][h * 2 + 0] + bias[gn]);
                const float v1 = gelu_exact(c[mf][nf][h * 2 + 1] + bias[gn + 1]);
                *(__half2*)&g_H[(size_t)gm * HID + gn] = __floats2half2_rn(v0, v1);
            }
}

/* ---------------- fused: z=0 out-GEMM, z=1..8 expert e=z-1 ------------- */
__global__ __launch_bounds__(256, 2)
void fused_out_expert(const float* __restrict__ b2, const float* __restrict__ xres,
                      float* __restrict__ outp)
{
    extern __shared__ __half smf[];
    __shared__ int   stok[128];
    __shared__ float swt[128];

    const int tid  = threadIdx.x;
    const int lane = tid & 31, warp = tid >> 5;
    const int wm = warp >> 2, wn = warp & 3;
    const int m0 = blockIdx.x * BM;

    if (blockIdx.z == 0) {
        const int n0 = blockIdx.y * BN;
        const __half* pAg = g_w2r + (size_t)m0 * HID;
        const __half* pBg = g_H + (size_t)n0 * HID;

        float c[4][4][4];
#pragma unroll
        for (int i = 0; i < 4; i++)
#pragma unroll
            for (int j = 0; j < 4; j++)
#pragma unroll
                for (int q = 0; q < 4; q++) c[i][j][q] = 0.f;

        MAINLOOP_BODY(HID / BK, HID)

#pragma unroll
        for (int mf = 0; mf < 4; mf++)
#pragma unroll
            for (int nf = 0; nf < 4; nf++)
#pragma unroll
                for (int h = 0; h < 2; h++) {
                    const int gm = m0 + wm * 64 + mf * 16 + (lane >> 2) + h * 8;
                    const int gn = n0 + wn * 32 + nf * 8 + (lane & 3) * 2;
                    const size_t off = (size_t)(gn >> 10) * BSTR + (size_t)gm * 1024 + (gn & 1023);
                    const float2 xr = *(const float2*)&xres[off];
                    const float bv = b2[gm];
                    *(float2*)&outp[off] = make_float2(xr.x + c[mf][nf][h*2] + bv,
                                                       xr.y + c[mf][nf][h*2+1] + bv);
                }
    } else {
        const int e   = blockIdx.z - 1;
        const int n_e = g_cnt[e];
        const int n0  = blockIdx.y * 128;
        if (n0 >= n_e) return;

        if (tid < 128) {
            const int j = n0 + tid;
            stok[tid] = (j < n_e) ? g_btok[e * T_TOK + j] : -1;
            swt [tid] = (j < n_e) ? g_bwt [e * T_TOK + j] : 0.f;
        }
        __syncthreads();

        const __half* pAg = g_wupT + (size_t)e * CIN * DLOW + (size_t)m0 * DLOW;
        const __half* pBg = g_Bex  + ((size_t)e * T_TOK + n0) * DLOW;

        float c[4][4][4];
#pragma unroll
        for (int i = 0; i < 4; i++)
#pragma unroll
            for (int j = 0; j < 4; j++)
#pragma unroll
                for (int q = 0; q < 4; q++) c[i][j][q] = 0.f;

        MAINLOOP_BODY(DLOW / BK, DLOW)

#pragma unroll
        for (int mf = 0; mf < 4; mf++)
#pragma unroll
            for (int nf = 0; nf < 4; nf++)
#pragma unroll
                for (int h = 0; h < 2; h++) {
                    const int gm = m0 + wm * 64 + mf * 16 + (lane >> 2) + h * 8;
                    const int col0 = wn * 32 + nf * 8 + (lane & 3) * 2;
#pragma unroll
                    for (int q = 0; q < 2; q++) {
                        const int col = col0 + q;
                        const int tk = stok[col];
                        if (tk < 0) continue;
                        atomicAdd(&g_aoe[(size_t)(tk >> 10) * BSTR +
                                         (size_t)gm * 1024 + (tk & 1023)],
                                  c[mf][nf][h * 2 + q] * swt[col]);
                    }
                }
    }
}

/* ---------------- final: out += aoe ---------------- */
__global__ __launch_bounds__(256)
void final_add_kernel(float* __restrict__ out) {
    const int stride = gridDim.x * 256;
    for (int i = blockIdx.x * 256 + threadIdx.x; i < N4_AOE; i += stride) {
        float4 o = ((const float4*)out)[i];
        const float4 a = ((const float4*)g_aoe)[i];
        o.x += a.x; o.y += a.y; o.z += a.z; o.w += a.w;
        ((float4*)out)[i] = o;
    }
}

/* ---------------- aux loss ---------------- */
__global__ __launch_bounds__(256)
void aux_kernel(float* __restrict__ out, int out_size)
{
    __shared__ float red[NEXP][256];
    const int tid = threadIdx.x;
    for (int e = 0; e < NEXP; e++) {
        float s = 0.f;
        for (int t = tid; t < T_TOK; t += 256) s += g_probsT[e * T_TOK + t];
        red[e][tid] = s;
    }
    __syncthreads();
    for (int off = 128; off; off >>= 1) {
        if (tid < off)
            for (int e = 0; e < NEXP; e++) red[e][tid] += red[e][tid + off];
        __syncthreads();
    }
    if (tid == 0) {
        float aux = 0.f;
        for (int e = 0; e < NEXP; e++)
            aux += (red[e][0] / (float)T_TOK) * ((float)g_cnt[e] / (float)T_TOK);
        aux *= (float)NEXP;
        for (int i = MAIN_SIZE; i < out_size; i++) out[i] = aux;
    }
}

/* ---------------- launch ---------------- */
extern "C" void kernel_launch(void* const* d_in, const int* in_sizes, int n_in,
                              void* d_out, int out_size)
{
    const float* x        = (const float*)d_in[0];
    const float* w1       = (const float*)d_in[1];
    const float* b1       = (const float*)d_in[2];
    const float* w2       = (const float*)d_in[3];
    const float* b2       = (const float*)d_in[4];
    const float* w_down   = (const float*)d_in[5];
    const float* router_w = (const float*)d_in[6];
    const float* w_up     = (const float*)d_in[7];
    float* out = (float*)d_out;

    static cudaStream_t s2 = nullptr;
    static cudaEvent_t evFork = nullptr, evSide = nullptr;
    if (!s2) {
        cudaStreamCreateWithFlags(&s2, cudaStreamNonBlocking);
        cudaEventCreateWithFlags(&evFork, cudaEventDisableTiming);
        cudaEventCreateWithFlags(&evSide, cudaEventDisableTiming);
        cudaFuncSetAttribute(gemm0_kernel, cudaFuncAttributeMaxDynamicSharedMemorySize, SMEM_BYTES);
        cudaFuncSetAttribute(fused_out_expert, cudaFuncAttributeMaxDynamicSharedMemorySize, SMEM_BYTES);
        cudaFuncSetAttribute(feats_gemm_kernel, cudaFuncAttributeMaxDynamicSharedMemorySize, FB_SMEM);
    }

    /* side stream: input-only work starts IMMEDIATELY (overlaps prep/transpose) */
    wupT_kernel<<<dim3(24, 6, 8), dim3(32, 8), 0, s2>>>(w_up);
    precompC_part_kernel<<<dim3(NEXP, DCHUNKS), CIN, 0, s2>>>(w_down, router_w);
    precompC_reduce_kernel<<<(CIN * NEXP + 255) / 256, 256, 0, s2>>>();

    /* main stream: weights + x prep */
    prep_kernel<<<592, 256>>>(w1, w_down, w2);
    transpose_x_kernel<<<dim3(32, 24, 8), dim3(32, 8)>>>(x);
    cudaEventRecord(evFork, 0);   /* prep + transpose both done */

    /* side stream (after fork): router + aux + feats (feats needs g_wdh+g_xTr) */
    cudaStreamWaitEvent(s2, evFork, 0);
    router_kernel<<<128, 256, 0, s2>>>();
    aux_kernel<<<1, 256, 0, s2>>>(out, out_size);
    feats_gemm_kernel<<<dim3(DLOW / 64, 64, NEXP), 256, FB_SMEM, s2>>>();
    cudaEventRecord(evSide, s2);

    gemm0_kernel<<<dim3(64, HID / 128), 256, SMEM_BYTES>>>(b1);

    /* tail: out-GEMM + expert GEMMs fused in one launch, then fold aoe */
    cudaStreamWaitEvent(0, evSide, 0);
    fused_out_expert<<<dim3(6, 64, NEXP + 1), 256, SMEM_BYTES>>>(b2, x, out);
    final_add_kernel<<<592, 256>>>(out);
}